// round 3
// baseline (speedup 1.0000x reference)
#include <cuda_runtime.h>

// Fixed problem shapes
#define DD 160
#define HH 192
#define WW 160
static constexpr int VOL = DD * HH * WW;   // 4,915,200

// CTA tile of output voxels
#define TX 32
#define TY 16
#define TZ 8
// Haloed SMEM extents (low halo 6; high halo 7/6/6 incl. +1 corner)
#define EX 45     // x0 in [tileX-6, tileX+37], x1 <= tileX+38
#define EY 29     // y0 in [tileY-6, tileY+21]
#define EZ 21     // z0 in [tileZ-6, tileZ+13]
#define SMEM_ELEMS (EX * EY * EZ)   // 27,405 floats = 109,620 B

__global__ void __launch_bounds__(1024, 2)
st_warp_tiled_kernel(const float* __restrict__ src,
                     const float* __restrict__ flow1,
                     const float* __restrict__ flow2,
                     const float* __restrict__ rf_p,
                     float* __restrict__ out)
{
    extern __shared__ float s_src[];

    const int tileX = blockIdx.x * TX;
    const int tileY = blockIdx.y * TY;
    const int tileZ = blockIdx.z * TZ;

    const int tid = threadIdx.x;

    // ---- Stage the haloed src tile into shared memory (zero-filled OOB).
    {
        const int bx = tileX - 6;
        const int by = tileY - 6;
        const int bz = tileZ - 6;
        for (int idx = tid; idx < SMEM_ELEMS; idx += 1024) {
            const int xx = idx % EX;
            const int r  = idx / EX;
            const int yy = r % EY;
            const int zz = r / EY;
            const int gx = bx + xx;
            const int gy = by + yy;
            const int gz = bz + zz;
            float v = 0.0f;
            if ((unsigned)gx < (unsigned)WW &&
                (unsigned)gy < (unsigned)HH &&
                (unsigned)gz < (unsigned)DD) {
                v = __ldg(src + (gz * HH + gy) * WW + gx);
            }
            s_src[idx] = v;
        }
    }
    __syncthreads();

    const float rf = __ldg(rf_p);

    const int lane = tid & 31;
    const int warp = tid >> 5;

    // Each thread handles TX*TY*TZ/1024 = 4 voxels; lane = x, rows over (y,z).
    #pragma unroll
    for (int it = 0; it < (TX * TY * TZ) / 1024; it++) {
        const int r = warp + 32 * it;       // 0..127
        const int y = tileY + (r & (TY - 1));
        const int z = tileZ + (r >> 4);
        const int x = tileX + lane;
        const int i = (z * HH + y) * WW + x;

        // flow2 channels (d,h,w order)
        const float f2d = __ldg(flow2 + i);
        const float f2h = __ldg(flow2 + i + VOL);
        const float f2w = __ldg(flow2 + i + 2 * VOL);

        // ---- Stage 1: sample flow1 at grid + rf*flow2 (unnormalized coords
        // pushed through a normalized sampler -> out of bounds except near origin)
        const float gd = (float)z + f2d * rf;
        const float gh = (float)y + f2h * rf;
        const float gw = (float)x + f2w * rf;
        const float ix = ((gw + 1.0f) * (float)WW - 1.0f) * 0.5f;
        const float iy = ((gh + 1.0f) * (float)HH - 1.0f) * 0.5f;
        const float iz = ((gd + 1.0f) * (float)DD - 1.0f) * 0.5f;

        float w1d = 0.0f, w1h = 0.0f, w1w = 0.0f;
        if (ix > -1.0f && ix < (float)WW &&
            iy > -1.0f && iy < (float)HH &&
            iz > -1.0f && iz < (float)DD) {
            const float x0f = floorf(ix), y0f = floorf(iy), z0f = floorf(iz);
            const float tx = ix - x0f, ty = iy - y0f, tz = iz - z0f;
            const int x0 = (int)x0f, y0 = (int)y0f, z0 = (int)z0f;
            #pragma unroll
            for (int dz = 0; dz < 2; dz++) {
                #pragma unroll
                for (int dy = 0; dy < 2; dy++) {
                    #pragma unroll
                    for (int dx = 0; dx < 2; dx++) {
                        const int zc = z0 + dz, yc = y0 + dy, xc = x0 + dx;
                        if ((unsigned)zc < (unsigned)DD &&
                            (unsigned)yc < (unsigned)HH &&
                            (unsigned)xc < (unsigned)WW) {
                            const float wt = (dz ? tz : 1.0f - tz) *
                                             (dy ? ty : 1.0f - ty) *
                                             (dx ? tx : 1.0f - tx);
                            const int off = (zc * HH + yc) * WW + xc;
                            w1d += wt * __ldg(flow1 + off);
                            w1h += wt * __ldg(flow1 + off + VOL);
                            w1w += wt * __ldg(flow1 + off + 2 * VOL);
                        }
                    }
                }
            }
        }

        // ---- out_flow = flow1_warped + flow2
        const float ofd = w1d + f2d;
        const float ofh = w1h + f2h;
        const float ofw = w1w + f2w;
        out[VOL + i]           = ofd;
        out[VOL + i + VOL]     = ofh;
        out[VOL + i + 2 * VOL] = ofw;

        // ---- Stage 2: normalized sample of src at grid + rf*out_flow
        const float nd = (float)z + ofd * rf;
        const float nh = (float)y + ofh * rf;
        const float nw = (float)x + ofw * rf;
        const float nld = 2.0f * (nd / (float)(DD - 1) - 0.5f);
        const float nlh = 2.0f * (nh / (float)(HH - 1) - 0.5f);
        const float nlw = 2.0f * (nw / (float)(WW - 1) - 0.5f);
        const float jx = ((nlw + 1.0f) * (float)WW - 1.0f) * 0.5f;
        const float jy = ((nlh + 1.0f) * (float)HH - 1.0f) * 0.5f;
        const float jz = ((nld + 1.0f) * (float)DD - 1.0f) * 0.5f;

        float val = 0.0f;
        const float x0f = floorf(jx), y0f = floorf(jy), z0f = floorf(jz);
        const float tx = jx - x0f, ty = jy - y0f, tz = jz - z0f;
        const int x0 = (int)x0f, y0 = (int)y0f, z0 = (int)z0f;

        // SMEM-local coordinates
        const int lx = x0 - (tileX - 6);
        const int ly = y0 - (tileY - 6);
        const int lz = z0 - (tileZ - 6);

        if ((unsigned)lx < (unsigned)(EX - 1) &&
            (unsigned)ly < (unsigned)(EY - 1) &&
            (unsigned)lz < (unsigned)(EZ - 1)) {
            // Fast path: all 8 corners inside the zero-filled SMEM tile.
            // Zero fill == padding_mode 'zeros' (w * 0 contribution).
            const int base = (lz * EY + ly) * EX + lx;
            const float v000 = s_src[base];
            const float v001 = s_src[base + 1];
            const float v010 = s_src[base + EX];
            const float v011 = s_src[base + EX + 1];
            const float v100 = s_src[base + EX * EY];
            const float v101 = s_src[base + EX * EY + 1];
            const float v110 = s_src[base + EX * EY + EX];
            const float v111 = s_src[base + EX * EY + EX + 1];
            const float wx0 = 1.0f - tx, wy0 = 1.0f - ty, wz0 = 1.0f - tz;
            val = wz0 * (wy0 * (wx0 * v000 + tx * v001) +
                         ty  * (wx0 * v010 + tx * v011)) +
                  tz  * (wy0 * (wx0 * v100 + tx * v101) +
                         ty  * (wx0 * v110 + tx * v111));
        } else if (jx > -1.0f && jx < (float)WW &&
                   jy > -1.0f && jy < (float)HH &&
                   jz > -1.0f && jz < (float)DD) {
            // Rare fallback: displacement exceeded halo — exact global gather.
            #pragma unroll
            for (int dz = 0; dz < 2; dz++) {
                #pragma unroll
                for (int dy = 0; dy < 2; dy++) {
                    #pragma unroll
                    for (int dx = 0; dx < 2; dx++) {
                        const int zc = z0 + dz, yc = y0 + dy, xc = x0 + dx;
                        if ((unsigned)zc < (unsigned)DD &&
                            (unsigned)yc < (unsigned)HH &&
                            (unsigned)xc < (unsigned)WW) {
                            const float wt = (dz ? tz : 1.0f - tz) *
                                             (dy ? ty : 1.0f - ty) *
                                             (dx ? tx : 1.0f - tx);
                            val += wt * __ldg(src + (zc * HH + yc) * WW + xc);
                        }
                    }
                }
            }
        }
        out[i] = val;
    }
}

extern "C" void kernel_launch(void* const* d_in, const int* in_sizes, int n_in,
                              void* d_out, int out_size)
{
    const float* src   = (const float*)d_in[0];
    const float* flow1 = (const float*)d_in[1];
    const float* flow2 = (const float*)d_in[2];
    // d_in[3] (meshgrid) recomputed analytically in-kernel.
    const float* rf    = (const float*)d_in[4];
    float* out = (float*)d_out;

    const int smem_bytes = SMEM_ELEMS * (int)sizeof(float);
    cudaFuncSetAttribute(st_warp_tiled_kernel,
                         cudaFuncAttributeMaxDynamicSharedMemorySize, smem_bytes);

    dim3 grid(WW / TX, HH / TY, DD / TZ);   // 5 x 12 x 20 = 1200 CTAs
    st_warp_tiled_kernel<<<grid, 1024, smem_bytes>>>(src, flow1, flow2, rf, out);
}

// round 6
// speedup vs baseline: 1.4622x; 1.4622x over previous
#include <cuda_runtime.h>

// Fixed problem shapes
#define DD 160
#define HH 192
#define WW 160
static constexpr int VOL = DD * HH * WW;   // 4,915,200

// CTA tile of output voxels
#define TX 32
#define TY 16
#define TZ 16
// Haloed SMEM extents. Window origin: (tileX-8, tileY-6, tileZ-6).
// x: lx in [2,45], +1 <= 46 < 48.  y: ly in [0,27], +1 <= 28 < 32.
// z: lz in [0,27], +1 <= 28 < 29.
#define EX 48
#define EY 32
#define EZ 29
#define SMEM_ELEMS (EX * EY * EZ)          // 44,544 floats = 178,176 B
#define SMEM_VEC4  (SMEM_ELEMS / 4)        // 11,136 float4
static constexpr int STAGE_ITERS = (SMEM_VEC4 + 1023) / 1024;  // 11

__global__ void __launch_bounds__(1024, 1)
st_warp_tiled2_kernel(const float* __restrict__ src,
                      const float* __restrict__ flow1,
                      const float* __restrict__ flow2,
                      const float* __restrict__ rf_p,
                      float* __restrict__ out)
{
    extern __shared__ float s_src[];

    const int tileX = blockIdx.x * TX;
    const int tileY = blockIdx.y * TY;
    const int tileZ = blockIdx.z * TZ;
    const int tid = threadIdx.x;

    const int bx = tileX - 8;   // multiple of 4 -> float4-aligned gmem reads
    const int by = tileY - 6;
    const int bz = tileZ - 6;

    // ---- Stage haloed src tile into SMEM, float4 at a time, zero-filled OOB.
    #pragma unroll
    for (int it = 0; it < STAGE_ITERS; it++) {
        const int q = tid + it * 1024;
        if (q < SMEM_VEC4) {
            const int xq  = q % (EX / 4);        // 0..11 (magic-mul)
            const int row = q / (EX / 4);
            const int yy  = row & (EY - 1);      // EY pow2
            const int zz  = row >> 5;
            const int gx = bx + xq * 4;
            const int gy = by + yy;
            const int gz = bz + zz;
            float4 v = make_float4(0.f, 0.f, 0.f, 0.f);
            const bool yzok = ((unsigned)gy < (unsigned)HH) &
                              ((unsigned)gz < (unsigned)DD);
            if (yzok) {
                const float* p = src + (gz * HH + gy) * WW;
                if (gx >= 0 && gx + 3 < WW) {
                    v = __ldg((const float4*)(p + gx));
                } else {
                    if ((unsigned)(gx + 0) < (unsigned)WW) v.x = __ldg(p + gx + 0);
                    if ((unsigned)(gx + 1) < (unsigned)WW) v.y = __ldg(p + gx + 1);
                    if ((unsigned)(gx + 2) < (unsigned)WW) v.z = __ldg(p + gx + 2);
                    if ((unsigned)(gx + 3) < (unsigned)WW) v.w = __ldg(p + gx + 3);
                }
            }
            *(float4*)(s_src + q * 4) = v;
        }
    }
    __syncthreads();

    const float rf = __ldg(rf_p);

    // ---- Voxel work: each thread owns 2 chunks of 4 x-consecutive voxels.
    #pragma unroll
    for (int it = 0; it < 2; it++) {
        const int c  = tid + it * 1024;          // 0..2047
        const int xq = c & 7;                    // 8 x-chunks
        const int yy = (c >> 3) & 15;
        const int zz = c >> 7;                   // 0..15
        const int x0base = tileX + xq * 4;
        const int y = tileY + yy;
        const int z = tileZ + zz;
        const int i0 = (z * HH + y) * WW + x0base;

        const float4 f2d4 = __ldg((const float4*)(flow2 + i0));
        const float4 f2h4 = __ldg((const float4*)(flow2 + i0 + VOL));
        const float4 f2w4 = __ldg((const float4*)(flow2 + i0 + 2 * VOL));
        const float f2d_a[4] = {f2d4.x, f2d4.y, f2d4.z, f2d4.w};
        const float f2h_a[4] = {f2h4.x, f2h4.y, f2h4.z, f2h4.w};
        const float f2w_a[4] = {f2w4.x, f2w4.y, f2w4.z, f2w4.w};

        float img_a[4], ofd_a[4], ofh_a[4], ofw_a[4];

        #pragma unroll
        for (int j = 0; j < 4; j++) {
            const int x = x0base + j;
            const float f2d = f2d_a[j];
            const float f2h = f2h_a[j];
            const float f2w = f2w_a[j];

            // ---- Stage 1: sample flow1 at grid + rf*flow2 (unnormalized
            // coords through a normalized sampler -> OOB except near origin)
            const float gd = (float)z + f2d * rf;
            const float gh = (float)y + f2h * rf;
            const float gw = (float)x + f2w * rf;
            const float ix = ((gw + 1.0f) * (float)WW - 1.0f) * 0.5f;
            const float iy = ((gh + 1.0f) * (float)HH - 1.0f) * 0.5f;
            const float iz = ((gd + 1.0f) * (float)DD - 1.0f) * 0.5f;

            float w1d = 0.0f, w1h = 0.0f, w1w = 0.0f;
            if (ix > -1.0f && ix < (float)WW &&
                iy > -1.0f && iy < (float)HH &&
                iz > -1.0f && iz < (float)DD) {
                const float x0f = floorf(ix), y0f = floorf(iy), z0f = floorf(iz);
                const float tx = ix - x0f, ty = iy - y0f, tz = iz - z0f;
                const int x0 = (int)x0f, y0 = (int)y0f, z0 = (int)z0f;
                #pragma unroll
                for (int dz = 0; dz < 2; dz++)
                    #pragma unroll
                    for (int dy = 0; dy < 2; dy++)
                        #pragma unroll
                        for (int dx = 0; dx < 2; dx++) {
                            const int zc = z0 + dz, yc = y0 + dy, xc = x0 + dx;
                            if ((unsigned)zc < (unsigned)DD &&
                                (unsigned)yc < (unsigned)HH &&
                                (unsigned)xc < (unsigned)WW) {
                                const float wt = (dz ? tz : 1.0f - tz) *
                                                 (dy ? ty : 1.0f - ty) *
                                                 (dx ? tx : 1.0f - tx);
                                const int off = (zc * HH + yc) * WW + xc;
                                w1d += wt * __ldg(flow1 + off);
                                w1h += wt * __ldg(flow1 + off + VOL);
                                w1w += wt * __ldg(flow1 + off + 2 * VOL);
                            }
                        }
            }

            const float ofd = w1d + f2d;
            const float ofh = w1h + f2h;
            const float ofw = w1w + f2w;
            ofd_a[j] = ofd; ofh_a[j] = ofh; ofw_a[j] = ofw;

            // ---- Stage 2: normalized sample of src at grid + rf*out_flow
            const float nd = (float)z + ofd * rf;
            const float nh = (float)y + ofh * rf;
            const float nw = (float)x + ofw * rf;
            const float nld = 2.0f * (nd / (float)(DD - 1) - 0.5f);
            const float nlh = 2.0f * (nh / (float)(HH - 1) - 0.5f);
            const float nlw = 2.0f * (nw / (float)(WW - 1) - 0.5f);
            const float jx = ((nlw + 1.0f) * (float)WW - 1.0f) * 0.5f;
            const float jy = ((nlh + 1.0f) * (float)HH - 1.0f) * 0.5f;
            const float jz = ((nld + 1.0f) * (float)DD - 1.0f) * 0.5f;

            const float x0f = floorf(jx), y0f = floorf(jy), z0f = floorf(jz);
            const float tx = jx - x0f, ty = jy - y0f, tz = jz - z0f;
            const int x0 = (int)x0f, y0 = (int)y0f, z0 = (int)z0f;
            const int lx = x0 - bx;
            const int ly = y0 - by;
            const int lz = z0 - bz;

            float val = 0.0f;
            if ((unsigned)lx < (unsigned)(EX - 1) &&
                (unsigned)ly < (unsigned)(EY - 1) &&
                (unsigned)lz < (unsigned)(EZ - 1)) {
                // Fast path: all 8 corners inside zero-filled SMEM tile.
                const int base = (lz * EY + ly) * EX + lx;
                const float v000 = s_src[base];
                const float v001 = s_src[base + 1];
                const float v010 = s_src[base + EX];
                const float v011 = s_src[base + EX + 1];
                const float v100 = s_src[base + EX * EY];
                const float v101 = s_src[base + EX * EY + 1];
                const float v110 = s_src[base + EX * EY + EX];
                const float v111 = s_src[base + EX * EY + EX + 1];
                const float wx0 = 1.0f - tx, wy0 = 1.0f - ty, wz0 = 1.0f - tz;
                val = wz0 * (wy0 * (wx0 * v000 + tx * v001) +
                             ty  * (wx0 * v010 + tx * v011)) +
                      tz  * (wy0 * (wx0 * v100 + tx * v101) +
                             ty  * (wx0 * v110 + tx * v111));
            } else if (jx > -1.0f && jx < (float)WW &&
                       jy > -1.0f && jy < (float)HH &&
                       jz > -1.0f && jz < (float)DD) {
                // Rare fallback: exceeded halo — exact global gather.
                #pragma unroll
                for (int dz = 0; dz < 2; dz++)
                    #pragma unroll
                    for (int dy = 0; dy < 2; dy++)
                        #pragma unroll
                        for (int dx = 0; dx < 2; dx++) {
                            const int zc = z0 + dz, yc = y0 + dy, xc = x0 + dx;
                            if ((unsigned)zc < (unsigned)DD &&
                                (unsigned)yc < (unsigned)HH &&
                                (unsigned)xc < (unsigned)WW) {
                                const float wt = (dz ? tz : 1.0f - tz) *
                                                 (dy ? ty : 1.0f - ty) *
                                                 (dx ? tx : 1.0f - tx);
                                val += wt * __ldg(src + (zc * HH + yc) * WW + xc);
                            }
                        }
            }
            img_a[j] = val;
        }

        // Vectorized stores (i0 is 16B-aligned)
        *(float4*)(out + i0) = make_float4(img_a[0], img_a[1], img_a[2], img_a[3]);
        *(float4*)(out + VOL + i0) = make_float4(ofd_a[0], ofd_a[1], ofd_a[2], ofd_a[3]);
        *(float4*)(out + VOL + i0 + VOL) = make_float4(ofh_a[0], ofh_a[1], ofh_a[2], ofh_a[3]);
        *(float4*)(out + VOL + i0 + 2 * VOL) = make_float4(ofw_a[0], ofw_a[1], ofw_a[2], ofw_a[3]);
    }
}

extern "C" void kernel_launch(void* const* d_in, const int* in_sizes, int n_in,
                              void* d_out, int out_size)
{
    const float* src   = (const float*)d_in[0];
    const float* flow1 = (const float*)d_in[1];
    const float* flow2 = (const float*)d_in[2];
    // d_in[3] (meshgrid) recomputed analytically in-kernel.
    const float* rf    = (const float*)d_in[4];
    float* out = (float*)d_out;

    const int smem_bytes = SMEM_ELEMS * (int)sizeof(float);
    cudaFuncSetAttribute(st_warp_tiled2_kernel,
                         cudaFuncAttributeMaxDynamicSharedMemorySize, smem_bytes);

    dim3 grid(WW / TX, HH / TY, DD / TZ);   // 5 x 12 x 10 = 600 CTAs
    st_warp_tiled2_kernel<<<grid, 1024, smem_bytes>>>(src, flow1, flow2, rf, out);
}